// round 2
// baseline (speedup 1.0000x reference)
#include <cuda_runtime.h>
#include <cuda_bf16.h>

// Problem shape (fixed by setup_inputs)
#define BQ 8
#define SQ 4096
#define DD 1024
#define DH 512
#define MM (BQ * SQ)           // 32768 tokens

#define THRESHOLD 0.1f
#define EPSV 1e-05f

// GEMM tiling
#define BM 128
#define BN 128
#define BK 8
#define NG (DH / BN)           // 4 N-groups

// Device scratch (no cudaMalloc allowed)
__device__ float g_yp[NG][MM];     // per-N-group partial gate logits
__device__ float g_yfin[MM];       // final gate values (post adjust)
__device__ int   g_idx[BQ][SQ];    // compacted source indices per batch
__device__ int   g_newlen[BQ];

// ---------------------------------------------------------------------------
// Kernel A: fp32 SGEMM H = X @ W1 (128x128 tile over K=1024), fused epilogue
//           yp[group][token] = sum_j relu(h_j + b1_j) * W2_j   (group = N tile)
// ---------------------------------------------------------------------------
__global__ __launch_bounds__(256, 2)
void gemm_gate_kernel(const float* __restrict__ X,
                      const float* __restrict__ W1,
                      const float* __restrict__ b1,
                      const float* __restrict__ W2)
{
    __shared__ float As[BK][BM];
    __shared__ float Bs[BK][BN];
    __shared__ float red[BM][17];   // padded to avoid bank conflicts

    const int m0 = blockIdx.x * BM;
    const int n0 = blockIdx.y * BN;
    const int tid = threadIdx.x;
    const int tx = tid & 15;        // 0..15 -> 8 cols each
    const int ty = tid >> 4;        // 0..15 -> 8 rows each

    // global load indices
    const int lm = tid >> 1;          // 0..127 (X row within tile)
    const int lk = (tid & 1) * 4;     // 0 or 4 (k offset)
    const int wk = tid >> 5;          // 0..7   (W1 k row)
    const int wn = (tid & 31) * 4;    // 0..124 (W1 n offset)

    const float* Xp = X + (size_t)m0 * DD;
    const float* Wp = W1 + n0;

    float acc[8][8];
#pragma unroll
    for (int i = 0; i < 8; i++)
#pragma unroll
        for (int j = 0; j < 8; j++) acc[i][j] = 0.0f;

    for (int k0 = 0; k0 < DD; k0 += BK) {
        // Load X tile (transposed into smem)
        float4 xa = *(const float4*)(Xp + (size_t)lm * DD + k0 + lk);
        As[lk + 0][lm] = xa.x;
        As[lk + 1][lm] = xa.y;
        As[lk + 2][lm] = xa.z;
        As[lk + 3][lm] = xa.w;
        // Load W1 tile
        float4 wb = *(const float4*)(Wp + (size_t)(k0 + wk) * DH + wn);
        *(float4*)&Bs[wk][wn] = wb;
        __syncthreads();

#pragma unroll
        for (int k = 0; k < BK; k++) {
            float a[8], b[8];
            *(float4*)(a)     = *(const float4*)&As[k][ty * 8];
            *(float4*)(a + 4) = *(const float4*)&As[k][ty * 8 + 4];
            *(float4*)(b)     = *(const float4*)&Bs[k][tx * 8];
            *(float4*)(b + 4) = *(const float4*)&Bs[k][tx * 8 + 4];
#pragma unroll
            for (int i = 0; i < 8; i++)
#pragma unroll
                for (int j = 0; j < 8; j++)
                    acc[i][j] = fmaf(a[i], b[j], acc[i][j]);
        }
        __syncthreads();
    }

    // Epilogue: relu(h + b1) * w2, reduce the 128 N-columns of this tile.
    float w2v[8], b1v[8];
#pragma unroll
    for (int j = 0; j < 8; j++) {
        w2v[j] = W2[n0 + tx * 8 + j];
        b1v[j] = b1[n0 + tx * 8 + j];
    }
#pragma unroll
    for (int i = 0; i < 8; i++) {
        float p = 0.0f;
#pragma unroll
        for (int j = 0; j < 8; j++) {
            float h = acc[i][j] + b1v[j];
            p = fmaf(fmaxf(h, 0.0f), w2v[j], p);
        }
        red[ty * 8 + i][tx] = p;
    }
    __syncthreads();

    if (tid < BM) {
        float s = 0.0f;
#pragma unroll
        for (int t = 0; t < 16; t++) s += red[tid][t];
        g_yp[blockIdx.y][m0 + tid] = s;
    }
}

// ---------------------------------------------------------------------------
// Kernel B: per-batch gate squash, max/adjust, mask + stable compaction scan.
// One block per batch row, 256 threads.
// pad is read as 4-byte elements (int32 or float32): nonzero bits == padded.
// ---------------------------------------------------------------------------
__global__ __launch_bounds__(256, 1)
void gate_select_kernel(const unsigned int* __restrict__ pad,
                        const float* __restrict__ b2,
                        float* __restrict__ vpad_out,
                        int write_vpad)
{
    const int b = blockIdx.x;
    const int tid = threadIdx.x;

    __shared__ float ysm[SQ];       // 16 KB: gate values for this row
    __shared__ int   ired[256];
    __shared__ float fred[256];
    __shared__ int   cnt[256];

    // 1. valid length = count of pad==0 (pad is trailing)
    int lc = 0;
    for (int s = tid; s < SQ; s += 256)
        lc += (pad[b * SQ + s] == 0u) ? 1 : 0;
    ired[tid] = lc;
    __syncthreads();
    for (int o = 128; o > 0; o >>= 1) {
        if (tid < o) ired[tid] += ired[tid + o];
        __syncthreads();
    }
    const int length = ired[0];
    __syncthreads();

    // 2. squash logits, zero padded, row max
    const float b2v = b2[0];
    float mx = 0.0f;
    for (int s = tid; s < SQ; s += 256) {
        const int t = b * SQ + s;
        float ysum = 0.0f;
#pragma unroll
        for (int g = 0; g < NG; g++) ysum += g_yp[g][t];
        float y = (s < length) ? (1.0f + tanhf(10.0f * (ysum + b2v))) * 0.5f
                               : 0.0f;
        ysm[s] = y;
        mx = fmaxf(mx, y);
    }
    fred[tid] = mx;
    __syncthreads();
    for (int o = 128; o > 0; o >>= 1) {
        if (tid < o) fred[tid] = fmaxf(fred[tid], fred[tid + o]);
        __syncthreads();
    }
    const float adjust = fmaxf(0.0f, EPSV + THRESHOLD - fred[0]);
    __syncthreads();

    // 3. y_final = y + adjust (all positions), persist to global
    for (int s = tid; s < SQ; s += 256) {
        float yf = ysm[s] + adjust;
        ysm[s] = yf;
        g_yfin[b * SQ + s] = yf;
    }
    __syncthreads();

    // 4. stable compaction: blocked per-thread chunks + block scan
    const int CH = SQ / 256;        // 16 contiguous positions per thread
    const int base = tid * CH;
    int c = 0;
#pragma unroll
    for (int i = 0; i < CH; i++) {
        int s = base + i;
        c += (ysm[s] > THRESHOLD && s < length) ? 1 : 0;
    }
    cnt[tid] = c;
    __syncthreads();
    // inclusive Hillis-Steele scan (read-then-write with syncs)
    for (int o = 1; o < 256; o <<= 1) {
        int v = (tid >= o) ? cnt[tid - o] : 0;
        __syncthreads();
        cnt[tid] += v;
        __syncthreads();
    }
    int off = cnt[tid] - c;         // exclusive prefix
#pragma unroll
    for (int i = 0; i < CH; i++) {
        int s = base + i;
        if (ysm[s] > THRESHOLD && s < length) {
            g_idx[b][off++] = s;
        }
    }
    const int nl = cnt[255];
    if (tid == 0) g_newlen[b] = nl;

    // 5. optional v_pad output (as 0/1 floats appended after v)
    if (write_vpad) {
        for (int s = tid; s < SQ; s += 256)
            vpad_out[b * SQ + s] = (s >= nl) ? 1.0f : 0.0f;
    }
}

// ---------------------------------------------------------------------------
// Kernel C: scatter compacted rows. One block per (output row, batch).
// ---------------------------------------------------------------------------
__global__ __launch_bounds__(256, 4)
void scatter_kernel(const float* __restrict__ X, float* __restrict__ V)
{
    const int b = blockIdx.y;
    const int r = blockIdx.x;
    const int tid = threadIdx.x;
    const int nl = g_newlen[b];

    float4* vrow = (float4*)(V + ((size_t)b * SQ + r) * DD);
    if (r < nl) {
        const int s = g_idx[b][r];
        const float g = g_yfin[b * SQ + s];
        const float4* xrow = (const float4*)(X + ((size_t)b * SQ + s) * DD);
        float4 xv = xrow[tid];
        vrow[tid] = make_float4(xv.x * g, xv.y * g, xv.z * g, xv.w * g);
    } else {
        vrow[tid] = make_float4(0.0f, 0.0f, 0.0f, 0.0f);
    }
}

// ---------------------------------------------------------------------------
extern "C" void kernel_launch(void* const* d_in, const int* in_sizes, int n_in,
                              void* d_out, int out_size)
{
    const float*        x   = (const float*)d_in[0];
    const unsigned int* pad = (const unsigned int*)d_in[1];
    const float*        W1  = (const float*)d_in[2];
    const float*        b1  = (const float*)d_in[3];
    const float*        W2  = (const float*)d_in[4];
    const float*        b2  = (const float*)d_in[5];
    float* out = (float*)d_out;

    const long v_elems = (long)MM * DD;
    int write_vpad = (out_size > v_elems) ? 1 : 0;
    float* vpad = out + v_elems;

    dim3 gg(MM / BM, NG);
    gemm_gate_kernel<<<gg, 256>>>(x, W1, b1, W2);
    gate_select_kernel<<<BQ, 256>>>(pad, b2, vpad, write_vpad);
    scatter_kernel<<<dim3(SQ, BQ), 256>>>(x, out);
}

// round 4
// speedup vs baseline: 1.9252x; 1.9252x over previous
#include <cuda_runtime.h>
#include <cuda_bf16.h>
#include <cstdint>

// Problem shape (fixed by setup_inputs)
#define BQ 8
#define SQ 4096
#define DD 1024
#define DH 512
#define MM (BQ * SQ)           // 32768 tokens

#define THRESHOLD 0.1f
#define EPSV 1e-05f
#define ZTHR (-0.10986122886681098f)   // atanh(2*0.1-1)/10
#define BAND 5e-4f
#define MAXFLAG 8192

// GEMM tiling
#define TM 128                 // tokens per CTA
#define TN 128                 // hidden units per CTA
#define BK 64                  // K per chunk
#define NCH (DD / BK)          // 16
#define NG (DH / TN)           // 4 N-groups

// smem layout (bytes)
#define SM_B1   0              // 128 floats
#define SM_W2   512
#define SM_RED  1024           // float[128][2]
#define SM_A    2048           // [stage][split] 4 x 16384
#define SM_B    (SM_A + 4*16384)
#define SM_TOT  (SM_B + 4*16384)   // 133120

// Device scratch
__device__ __nv_bfloat16 g_w1t[2][DH * DD];  // [split][n*DD + k] transposed W1
__device__ float g_yp[NG][MM];               // per-N-group partial logits
__device__ float g_z[MM];                    // full logits (incl b2)
__device__ float g_yfin[MM];                 // final gate values
__device__ int   g_idx[BQ][SQ];
__device__ int   g_newlen[BQ];
__device__ int   g_nflag;
__device__ int   g_flag[MAXFLAG];

// ---------------------------------------------------------------------------
__device__ __forceinline__ uint32_t smem_u32(const void* p) {
    uint32_t a;
    asm("{ .reg .u64 t; cvta.to.shared.u64 t, %1; cvt.u32.u64 %0, t; }"
        : "=r"(a) : "l"(p));
    return a;
}
__device__ __forceinline__ void ldm_x4(uint32_t& r0, uint32_t& r1,
                                       uint32_t& r2, uint32_t& r3, uint32_t addr) {
    asm volatile("ldmatrix.sync.aligned.m8n8.x4.shared.b16 {%0,%1,%2,%3}, [%4];"
                 : "=r"(r0), "=r"(r1), "=r"(r2), "=r"(r3) : "r"(addr));
}
__device__ __forceinline__ void mma_bf16(float* d, const uint32_t* a,
                                         uint32_t b0, uint32_t b1) {
    asm volatile(
        "mma.sync.aligned.m16n8k16.row.col.f32.bf16.bf16.f32 "
        "{%0,%1,%2,%3}, {%4,%5,%6,%7}, {%8,%9}, {%0,%1,%2,%3};"
        : "+f"(d[0]), "+f"(d[1]), "+f"(d[2]), "+f"(d[3])
        : "r"(a[0]), "r"(a[1]), "r"(a[2]), "r"(a[3]), "r"(b0), "r"(b1));
}
__device__ __forceinline__ void split2(float f0, float f1,
                                       uint32_t& hw, uint32_t& lw) {
    __nv_bfloat16 h0 = __float2bfloat16(f0);
    __nv_bfloat16 h1 = __float2bfloat16(f1);
    __nv_bfloat16 l0 = __float2bfloat16(f0 - __bfloat162float(h0));
    __nv_bfloat16 l1 = __float2bfloat16(f1 - __bfloat162float(h1));
    hw = (uint32_t)__bfloat16_as_ushort(h0) | ((uint32_t)__bfloat16_as_ushort(h1) << 16);
    lw = (uint32_t)__bfloat16_as_ushort(l0) | ((uint32_t)__bfloat16_as_ushort(l1) << 16);
}

// ---------------------------------------------------------------------------
// Kernel 0: transpose + 2-way bf16 split of W1; reset flag counter.
// ---------------------------------------------------------------------------
__global__ void w1_split_kernel(const float* __restrict__ W1) {
    const int n = blockIdx.x;
    if (n == 0 && threadIdx.x == 0) g_nflag = 0;
    for (int k = threadIdx.x; k < DD; k += blockDim.x) {
        float a = W1[(size_t)k * DH + n];
        __nv_bfloat16 h = __float2bfloat16(a);
        __nv_bfloat16 l = __float2bfloat16(a - __bfloat162float(h));
        g_w1t[0][(size_t)n * DD + k] = h;
        g_w1t[1][(size_t)n * DD + k] = l;
    }
}

// ---------------------------------------------------------------------------
// Kernel A: HMMA bf16x2 (3-product) emulated-fp32 GEMM + fused gate epilogue.
// grid (NG, MM/TM): N-group fastest so 4 CTAs share each X tile in L2.
// ---------------------------------------------------------------------------
__global__ __launch_bounds__(256, 1)
void gemm_hmma(const float* __restrict__ X,
               const float* __restrict__ b1,
               const float* __restrict__ W2)
{
    extern __shared__ char smem[];
    const uint32_t sbase = smem_u32(smem);
    const int tid = threadIdx.x;
    const int wid = tid >> 5;
    const int lane = tid & 31;
    const int wm = wid & 3;          // M quadrant (32 rows)
    const int wn = wid >> 2;         // N half (64 cols)
    const int n0 = blockIdx.x * TN;
    const int m0 = blockIdx.y * TM;

    float* b1s = (float*)(smem + SM_B1);
    float* w2s = (float*)(smem + SM_W2);
    float (*red)[2] = (float(*)[2])(smem + SM_RED);
    if (tid < TN) {
        b1s[tid] = b1[n0 + tid];
        w2s[tid] = W2[n0 + tid];
    }

    float acc[2][8][4];
#pragma unroll
    for (int mt = 0; mt < 2; mt++)
#pragma unroll
        for (int nt = 0; nt < 8; nt++)
#pragma unroll
            for (int e = 0; e < 4; e++) acc[mt][nt][e] = 0.0f;

    // Staging registers
    float4 av[2][4];          // A: 2 row-visits x 16 floats
    uint4  bv[2][2][2];       // B: [split][row-visit][2 x uint4]

    const int lrow = tid >> 2;           // 0..63
    const int lk16 = (tid & 3) * 16;     // element offset within chunk

    const float* Xp0 = X + (size_t)(m0 + lrow) * DD + lk16;
    const float* Xp1 = X + (size_t)(m0 + lrow + 64) * DD + lk16;
    const __nv_bfloat16* Bp[2][2];
#pragma unroll
    for (int sp = 0; sp < 2; sp++) {
        Bp[sp][0] = g_w1t[sp] + (size_t)(n0 + lrow) * DD + lk16;
        Bp[sp][1] = g_w1t[sp] + (size_t)(n0 + lrow + 64) * DD + lk16;
    }

#define LDG_CHUNK(c) do {                                                   \
    const int _k0 = (c) * BK;                                               \
    _Pragma("unroll")                                                       \
    for (int j = 0; j < 4; j++) {                                           \
        av[0][j] = *(const float4*)(Xp0 + _k0 + j * 4);                     \
        av[1][j] = *(const float4*)(Xp1 + _k0 + j * 4);                     \
    }                                                                       \
    _Pragma("unroll")                                                       \
    for (int sp = 0; sp < 2; sp++)                                          \
        _Pragma("unroll")                                                   \
        for (int rr = 0; rr < 2; rr++)                                      \
            _Pragma("unroll")                                               \
            for (int j = 0; j < 2; j++)                                     \
                bv[sp][rr][j] = *(const uint4*)(Bp[sp][rr] + _k0 + j * 8);  \
} while (0)

#define STS_CHUNK(st) do {                                                  \
    _Pragma("unroll")                                                       \
    for (int rr = 0; rr < 2; rr++) {                                        \
        const int row = lrow + rr * 64;                                     \
        const int rx = row & 7;                                             \
        const uint32_t rb = (uint32_t)row * 128u;                           \
        _Pragma("unroll")                                                   \
        for (int jj = 0; jj < 2; jj++) {                                    \
            const float* f = (const float*)&av[rr][jj * 2];                 \
            uint4 hi, lo;                                                   \
            split2(f[0], f[1], hi.x, lo.x);                                 \
            split2(f[2], f[3], hi.y, lo.y);                                 \
            split2(f[4], f[5], hi.z, lo.z);                                 \
            split2(f[6], f[7], hi.w, lo.w);                                 \
            const uint32_t ch = (uint32_t)((((tid & 3) * 2 + jj) ^ rx) * 16); \
            *(uint4*)(smem + SM_A + ((st) * 2 + 0) * 16384 + rb + ch) = hi; \
            *(uint4*)(smem + SM_A + ((st) * 2 + 1) * 16384 + rb + ch) = lo; \
            *(uint4*)(smem + SM_B + ((st) * 2 + 0) * 16384 + rb + ch) = bv[0][rr][jj]; \
            *(uint4*)(smem + SM_B + ((st) * 2 + 1) * 16384 + rb + ch) = bv[1][rr][jj]; \
        }                                                                   \
    }                                                                       \
} while (0)

    // Prologue
    LDG_CHUNK(0);
    STS_CHUNK(0);
    LDG_CHUNK(1);
    __syncthreads();

    for (int c = 0; c < NCH; c++) {
        const int st = c & 1;
        if (c + 1 < NCH) STS_CHUNK((c + 1) & 1);
        if (c + 2 < NCH) LDG_CHUNK(c + 2);

        // Compute from buf st
#pragma unroll
        for (int ks = 0; ks < 4; ks++) {
            uint32_t a[2][2][4];     // [split][mtile][4]
            uint32_t bb[2][4][4];    // [split][npair][4]
            const int cc = ks * 2 + (lane >> 4);
#pragma unroll
            for (int sp = 0; sp < 2; sp++)
#pragma unroll
                for (int mt = 0; mt < 2; mt++) {
                    const int r = wm * 32 + mt * 16 + (lane & 15);
                    const uint32_t addr = sbase + SM_A + (st * 2 + sp) * 16384
                                        + r * 128 + ((cc ^ (r & 7)) * 16);
                    ldm_x4(a[sp][mt][0], a[sp][mt][1], a[sp][mt][2], a[sp][mt][3], addr);
                }
#pragma unroll
            for (int sp = 0; sp < 2; sp++)
#pragma unroll
                for (int np = 0; np < 4; np++) {
                    const int r = wn * 64 + np * 16 + (lane & 15);
                    const uint32_t addr = sbase + SM_B + (st * 2 + sp) * 16384
                                        + r * 128 + ((cc ^ (r & 7)) * 16);
                    ldm_x4(bb[sp][np][0], bb[sp][np][1], bb[sp][np][2], bb[sp][np][3], addr);
                }
#pragma unroll
            for (int mt = 0; mt < 2; mt++)
#pragma unroll
                for (int nt = 0; nt < 8; nt++) {
                    const int np = nt >> 1, sel = nt & 1;
                    const uint32_t bh0 = bb[0][np][sel],     bh1 = bb[0][np][sel + 2];
                    const uint32_t bl0 = bb[1][np][sel],     bl1 = bb[1][np][sel + 2];
                    mma_bf16(acc[mt][nt], a[0][mt], bh0, bh1);   // hh
                    mma_bf16(acc[mt][nt], a[0][mt], bl0, bl1);   // hl
                    mma_bf16(acc[mt][nt], a[1][mt], bh0, bh1);   // lh
                }
        }
        __syncthreads();
    }

    // Epilogue: p = sum_cols relu(acc + b1) * w2, reduce across quads + wn.
#pragma unroll
    for (int mt = 0; mt < 2; mt++) {
        float p0 = 0.0f, p1 = 0.0f;
#pragma unroll
        for (int nt = 0; nt < 8; nt++) {
            const int cl = wn * 64 + nt * 8 + (lane & 3) * 2;
            const float w0 = w2s[cl], w1v = w2s[cl + 1];
            const float c0 = b1s[cl], c1 = b1s[cl + 1];
            p0 = fmaf(fmaxf(acc[mt][nt][0] + c0, 0.0f), w0, p0);
            p0 = fmaf(fmaxf(acc[mt][nt][1] + c1, 0.0f), w1v, p0);
            p1 = fmaf(fmaxf(acc[mt][nt][2] + c0, 0.0f), w0, p1);
            p1 = fmaf(fmaxf(acc[mt][nt][3] + c1, 0.0f), w1v, p1);
        }
        p0 += __shfl_xor_sync(0xffffffffu, p0, 1);
        p0 += __shfl_xor_sync(0xffffffffu, p0, 2);
        p1 += __shfl_xor_sync(0xffffffffu, p1, 1);
        p1 += __shfl_xor_sync(0xffffffffu, p1, 2);
        if ((lane & 3) == 0) {
            const int r0 = wm * 32 + mt * 16 + (lane >> 2);
            red[r0][wn] = p0;
            red[r0 + 8][wn] = p1;
        }
    }
    __syncthreads();
    if (tid < TM)
        g_yp[blockIdx.x][m0 + tid] = red[tid][0] + red[tid][1];
}

// ---------------------------------------------------------------------------
// Kernel B1: sum partials -> z, flag tokens within BAND of threshold.
// ---------------------------------------------------------------------------
__global__ __launch_bounds__(256, 8)
void zflag_kernel(const float* __restrict__ b2)
{
    const int t = blockIdx.x * 256 + threadIdx.x;
    float z = g_yp[0][t] + g_yp[1][t] + g_yp[2][t] + g_yp[3][t] + b2[0];
    g_z[t] = z;
    if (fabsf(z - ZTHR) < BAND) {
        int i = atomicAdd(&g_nflag, 1);
        if (i < MAXFLAG) g_flag[i] = t;
    }
}

// ---------------------------------------------------------------------------
// Kernel R: exact fp32 recompute of flagged tokens' logits.
// ---------------------------------------------------------------------------
__global__ __launch_bounds__(256, 1)
void refine_kernel(const float* __restrict__ X,
                   const float* __restrict__ W1,
                   const float* __restrict__ b1,
                   const float* __restrict__ W2,
                   const float* __restrict__ b2)
{
    __shared__ float xs[DD];
    __shared__ float rsum[256];
    const int tid = threadIdx.x;
    int n = g_nflag;
    if (n > MAXFLAG) n = MAXFLAG;

    for (int i = blockIdx.x; i < n; i += gridDim.x) {
        const int t = g_flag[i];
        for (int k = tid; k < DD; k += 256) xs[k] = X[(size_t)t * DD + k];
        __syncthreads();
        float p = 0.0f;
        for (int h = tid; h < DH; h += 256) {
            float a = 0.0f;
            for (int k = 0; k < DD; k++)
                a = fmaf(xs[k], W1[(size_t)k * DH + h], a);
            p = fmaf(fmaxf(a + b1[h], 0.0f), W2[h], p);
        }
        rsum[tid] = p;
        __syncthreads();
        for (int o = 128; o > 0; o >>= 1) {
            if (tid < o) rsum[tid] += rsum[tid + o];
            __syncthreads();
        }
        if (tid == 0) g_z[t] = rsum[0] + b2[0];
        __syncthreads();
    }
}

// ---------------------------------------------------------------------------
// Kernel B2: per-batch squash, max/adjust, compaction.
// pad read as 4-byte (int32/float32): nonzero == padded.
// ---------------------------------------------------------------------------
__global__ __launch_bounds__(256, 1)
void gate_select_kernel(const unsigned int* __restrict__ pad,
                        float* __restrict__ vpad_out,
                        int write_vpad)
{
    const int b = blockIdx.x;
    const int tid = threadIdx.x;

    __shared__ float ysm[SQ];
    __shared__ int   ired[256];
    __shared__ float fred[256];
    __shared__ int   cnt[256];

    int lc = 0;
    for (int s = tid; s < SQ; s += 256)
        lc += (pad[b * SQ + s] == 0u) ? 1 : 0;
    ired[tid] = lc;
    __syncthreads();
    for (int o = 128; o > 0; o >>= 1) {
        if (tid < o) ired[tid] += ired[tid + o];
        __syncthreads();
    }
    const int length = ired[0];
    __syncthreads();

    float mx = 0.0f;
    for (int s = tid; s < SQ; s += 256) {
        float y = (s < length)
                ? (1.0f + tanhf(10.0f * g_z[b * SQ + s])) * 0.5f : 0.0f;
        ysm[s] = y;
        mx = fmaxf(mx, y);
    }
    fred[tid] = mx;
    __syncthreads();
    for (int o = 128; o > 0; o >>= 1) {
        if (tid < o) fred[tid] = fmaxf(fred[tid], fred[tid + o]);
        __syncthreads();
    }
    const float adjust = fmaxf(0.0f, EPSV + THRESHOLD - fred[0]);
    __syncthreads();

    for (int s = tid; s < SQ; s += 256) {
        float yf = ysm[s] + adjust;
        ysm[s] = yf;
        g_yfin[b * SQ + s] = yf;
    }
    __syncthreads();

    const int CH = SQ / 256;
    const int base = tid * CH;
    int c = 0;
#pragma unroll
    for (int i = 0; i < CH; i++) {
        int s = base + i;
        c += (ysm[s] > THRESHOLD && s < length) ? 1 : 0;
    }
    cnt[tid] = c;
    __syncthreads();
    for (int o = 1; o < 256; o <<= 1) {
        int v = (tid >= o) ? cnt[tid - o] : 0;
        __syncthreads();
        cnt[tid] += v;
        __syncthreads();
    }
    int off = cnt[tid] - c;
#pragma unroll
    for (int i = 0; i < CH; i++) {
        int s = base + i;
        if (ysm[s] > THRESHOLD && s < length) g_idx[b][off++] = s;
    }
    const int nl = cnt[255];
    if (tid == 0) g_newlen[b] = nl;

    if (write_vpad) {
        for (int s = tid; s < SQ; s += 256)
            vpad_out[b * SQ + s] = (s >= nl) ? 1.0f : 0.0f;
    }
}

// ---------------------------------------------------------------------------
// Kernel C: scatter compacted rows.
// ---------------------------------------------------------------------------
__global__ __launch_bounds__(256, 4)
void scatter_kernel(const float* __restrict__ X, float* __restrict__ V)
{
    const int b = blockIdx.y;
    const int r = blockIdx.x;
    const int tid = threadIdx.x;
    const int nl = g_newlen[b];

    float4* vrow = (float4*)(V + ((size_t)b * SQ + r) * DD);
    if (r < nl) {
        const int s = g_idx[b][r];
        const float g = g_yfin[b * SQ + s];
        const float4* xrow = (const float4*)(X + ((size_t)b * SQ + s) * DD);
        float4 xv = xrow[tid];
        vrow[tid] = make_float4(xv.x * g, xv.y * g, xv.z * g, xv.w * g);
    } else {
        vrow[tid] = make_float4(0.0f, 0.0f, 0.0f, 0.0f);
    }
}

// ---------------------------------------------------------------------------
extern "C" void kernel_launch(void* const* d_in, const int* in_sizes, int n_in,
                              void* d_out, int out_size)
{
    const float*        x   = (const float*)d_in[0];
    const unsigned int* pad = (const unsigned int*)d_in[1];
    const float*        W1  = (const float*)d_in[2];
    const float*        b1  = (const float*)d_in[3];
    const float*        W2  = (const float*)d_in[4];
    const float*        b2  = (const float*)d_in[5];
    float* out = (float*)d_out;

    const long v_elems = (long)MM * DD;
    int write_vpad = (out_size > v_elems) ? 1 : 0;
    float* vpad = out + v_elems;

    cudaFuncSetAttribute(gemm_hmma,
                         cudaFuncAttributeMaxDynamicSharedMemorySize, SM_TOT);

    w1_split_kernel<<<DH, 256>>>(W1);
    gemm_hmma<<<dim3(NG, MM / TM), 256, SM_TOT>>>(x, b1, W2);
    zflag_kernel<<<MM / 256, 256>>>(b2);
    refine_kernel<<<64, 256>>>(x, W1, b1, W2, b2);
    gate_select_kernel<<<BQ, 256>>>(pad, vpad, write_vpad);
    scatter_kernel<<<dim3(SQ, BQ), 256>>>(x, out);
}

// round 5
// speedup vs baseline: 1.9766x; 1.0267x over previous
#include <cuda_runtime.h>
#include <cuda_bf16.h>
#include <cstdint>

// Problem shape (fixed by setup_inputs)
#define BQ 8
#define SQ 4096
#define DD 1024
#define DH 512
#define MM (BQ * SQ)           // 32768 tokens

#define THRESHOLD 0.1f
#define EPSV 1e-05f
#define ZTHR (-0.10986122886681098f)   // atanh(2*0.1-1)/10
#define BAND 5e-4f
#define MAXFLAG 8192

// GEMM tiling
#define TM 128                 // tokens per CTA
#define TN 128                 // hidden units per CTA
#define BK 64                  // K per chunk
#define NCH (DD / BK)          // 16
#define NG (DH / TN)           // 4 N-groups

// smem layout (bytes)
#define SM_B1   0              // 128 floats
#define SM_W2   512
#define SM_RED  1024           // float[128][2]
#define SM_A    2048           // [stage][split] 4 x 16384
#define SM_B    (SM_A + 4*16384)
#define SM_TOT  (SM_B + 4*16384)   // 133120

// Device scratch
__device__ __nv_bfloat16 g_w1t[2][DH * DD];  // [split][n*DD + k] transposed W1
__device__ float g_yp[NG][MM];               // per-N-group partial logits
__device__ float g_z[MM];                    // full logits (incl b2)
__device__ float g_yfin[MM];                 // final gate values
__device__ int   g_idx[BQ][SQ];
__device__ int   g_newlen[BQ];
__device__ int   g_nflag;
__device__ int   g_flag[MAXFLAG];

// ---------------------------------------------------------------------------
__device__ __forceinline__ uint32_t smem_u32(const void* p) {
    uint32_t a;
    asm("{ .reg .u64 t; cvta.to.shared.u64 t, %1; cvt.u32.u64 %0, t; }"
        : "=r"(a) : "l"(p));
    return a;
}
__device__ __forceinline__ void ldm_x4(uint32_t& r0, uint32_t& r1,
                                       uint32_t& r2, uint32_t& r3, uint32_t addr) {
    asm volatile("ldmatrix.sync.aligned.m8n8.x4.shared.b16 {%0,%1,%2,%3}, [%4];"
                 : "=r"(r0), "=r"(r1), "=r"(r2), "=r"(r3) : "r"(addr));
}
__device__ __forceinline__ void mma_bf16(float* d, const uint32_t* a,
                                         uint32_t b0, uint32_t b1) {
    asm volatile(
        "mma.sync.aligned.m16n8k16.row.col.f32.bf16.bf16.f32 "
        "{%0,%1,%2,%3}, {%4,%5,%6,%7}, {%8,%9}, {%0,%1,%2,%3};"
        : "+f"(d[0]), "+f"(d[1]), "+f"(d[2]), "+f"(d[3])
        : "r"(a[0]), "r"(a[1]), "r"(a[2]), "r"(a[3]), "r"(b0), "r"(b1));
}
__device__ __forceinline__ void split2(float f0, float f1,
                                       uint32_t& hw, uint32_t& lw) {
    __nv_bfloat16 h0 = __float2bfloat16(f0);
    __nv_bfloat16 h1 = __float2bfloat16(f1);
    __nv_bfloat16 l0 = __float2bfloat16(f0 - __bfloat162float(h0));
    __nv_bfloat16 l1 = __float2bfloat16(f1 - __bfloat162float(h1));
    hw = (uint32_t)__bfloat16_as_ushort(h0) | ((uint32_t)__bfloat16_as_ushort(h1) << 16);
    lw = (uint32_t)__bfloat16_as_ushort(l0) | ((uint32_t)__bfloat16_as_ushort(l1) << 16);
}

// ---------------------------------------------------------------------------
// Kernel 0: coalesced tiled transpose + 2-way bf16 split of W1.
// Grid (DD/32, DH/32), block 32x8. Reads W1[k][n] coalesced, writes
// g_w1t[s][n*DD + k] coalesced via smem tile.
// ---------------------------------------------------------------------------
__global__ __launch_bounds__(256, 6)
void w1_split_kernel(const float* __restrict__ W1) {
    __shared__ float tile[32][33];
    const int k0 = blockIdx.x * 32;
    const int n0 = blockIdx.y * 32;
    const int tx = threadIdx.x;   // 0..31
    const int ty = threadIdx.y;   // 0..7

    if (blockIdx.x == 0 && blockIdx.y == 0 && tx == 0 && ty == 0) g_nflag = 0;

#pragma unroll
    for (int j = 0; j < 4; j++) {
        const int k = k0 + ty + j * 8;
        tile[ty + j * 8][tx] = W1[(size_t)k * DH + n0 + tx];
    }
    __syncthreads();

#pragma unroll
    for (int j = 0; j < 4; j++) {
        const int n = n0 + ty + j * 8;
        const float a = tile[tx][ty + j * 8];
        __nv_bfloat16 h = __float2bfloat16(a);
        __nv_bfloat16 l = __float2bfloat16(a - __bfloat162float(h));
        g_w1t[0][(size_t)n * DD + k0 + tx] = h;
        g_w1t[1][(size_t)n * DD + k0 + tx] = l;
    }
}

// ---------------------------------------------------------------------------
// Kernel A: HMMA bf16x2 (3-product) emulated-fp32 GEMM + fused gate epilogue.
// grid (NG, MM/TM): N-group fastest so 4 CTAs share each X tile in L2.
// ---------------------------------------------------------------------------
__global__ __launch_bounds__(256, 1)
void gemm_hmma(const float* __restrict__ X,
               const float* __restrict__ b1,
               const float* __restrict__ W2)
{
    extern __shared__ char smem[];
    const uint32_t sbase = smem_u32(smem);
    const int tid = threadIdx.x;
    const int wid = tid >> 5;
    const int lane = tid & 31;
    const int wm = wid & 3;          // M quadrant (32 rows)
    const int wn = wid >> 2;         // N half (64 cols)
    const int n0 = blockIdx.x * TN;
    const int m0 = blockIdx.y * TM;

    float* b1s = (float*)(smem + SM_B1);
    float* w2s = (float*)(smem + SM_W2);
    float (*red)[2] = (float(*)[2])(smem + SM_RED);
    if (tid < TN) {
        b1s[tid] = b1[n0 + tid];
        w2s[tid] = W2[n0 + tid];
    }

    float acc[2][8][4];
#pragma unroll
    for (int mt = 0; mt < 2; mt++)
#pragma unroll
        for (int nt = 0; nt < 8; nt++)
#pragma unroll
            for (int e = 0; e < 4; e++) acc[mt][nt][e] = 0.0f;

    // Staging registers
    float4 av[2][4];          // A: 2 row-visits x 16 floats
    uint4  bv[2][2][2];       // B: [split][row-visit][2 x uint4]

    const int lrow = tid >> 2;           // 0..63
    const int lk16 = (tid & 3) * 16;     // element offset within chunk

    const float* Xp0 = X + (size_t)(m0 + lrow) * DD + lk16;
    const float* Xp1 = X + (size_t)(m0 + lrow + 64) * DD + lk16;
    const __nv_bfloat16* Bp[2][2];
#pragma unroll
    for (int sp = 0; sp < 2; sp++) {
        Bp[sp][0] = g_w1t[sp] + (size_t)(n0 + lrow) * DD + lk16;
        Bp[sp][1] = g_w1t[sp] + (size_t)(n0 + lrow + 64) * DD + lk16;
    }

#define LDG_CHUNK(c) do {                                                   \
    const int _k0 = (c) * BK;                                               \
    _Pragma("unroll")                                                       \
    for (int j = 0; j < 4; j++) {                                           \
        av[0][j] = *(const float4*)(Xp0 + _k0 + j * 4);                     \
        av[1][j] = *(const float4*)(Xp1 + _k0 + j * 4);                     \
    }                                                                       \
    _Pragma("unroll")                                                       \
    for (int sp = 0; sp < 2; sp++)                                          \
        _Pragma("unroll")                                                   \
        for (int rr = 0; rr < 2; rr++)                                      \
            _Pragma("unroll")                                               \
            for (int j = 0; j < 2; j++)                                     \
                bv[sp][rr][j] = *(const uint4*)(Bp[sp][rr] + _k0 + j * 8);  \
} while (0)

#define STS_CHUNK(st) do {                                                  \
    _Pragma("unroll")                                                       \
    for (int rr = 0; rr < 2; rr++) {                                        \
        const int row = lrow + rr * 64;                                     \
        const int rx = row & 7;                                             \
        const uint32_t rb = (uint32_t)row * 128u;                           \
        _Pragma("unroll")                                                   \
        for (int jj = 0; jj < 2; jj++) {                                    \
            const float* f = (const float*)&av[rr][jj * 2];                 \
            uint4 hi, lo;                                                   \
            split2(f[0], f[1], hi.x, lo.x);                                 \
            split2(f[2], f[3], hi.y, lo.y);                                 \
            split2(f[4], f[5], hi.z, lo.z);                                 \
            split2(f[6], f[7], hi.w, lo.w);                                 \
            const uint32_t ch = (uint32_t)((((tid & 3) * 2 + jj) ^ rx) * 16); \
            *(uint4*)(smem + SM_A + ((st) * 2 + 0) * 16384 + rb + ch) = hi; \
            *(uint4*)(smem + SM_A + ((st) * 2 + 1) * 16384 + rb + ch) = lo; \
            *(uint4*)(smem + SM_B + ((st) * 2 + 0) * 16384 + rb + ch) = bv[0][rr][jj]; \
            *(uint4*)(smem + SM_B + ((st) * 2 + 1) * 16384 + rb + ch) = bv[1][rr][jj]; \
        }                                                                   \
    }                                                                       \
} while (0)

    // Prologue
    LDG_CHUNK(0);
    STS_CHUNK(0);
    LDG_CHUNK(1);
    __syncthreads();

    for (int c = 0; c < NCH; c++) {
        const int st = c & 1;
        if (c + 1 < NCH) STS_CHUNK((c + 1) & 1);
        if (c + 2 < NCH) LDG_CHUNK(c + 2);

        // Compute from buf st
#pragma unroll
        for (int ks = 0; ks < 4; ks++) {
            uint32_t a[2][2][4];     // [split][mtile][4]
            uint32_t bb[2][4][4];    // [split][npair][4]
            const int cc = ks * 2 + (lane >> 4);
#pragma unroll
            for (int sp = 0; sp < 2; sp++)
#pragma unroll
                for (int mt = 0; mt < 2; mt++) {
                    const int r = wm * 32 + mt * 16 + (lane & 15);
                    const uint32_t addr = sbase + SM_A + (st * 2 + sp) * 16384
                                        + r * 128 + ((cc ^ (r & 7)) * 16);
                    ldm_x4(a[sp][mt][0], a[sp][mt][1], a[sp][mt][2], a[sp][mt][3], addr);
                }
#pragma unroll
            for (int sp = 0; sp < 2; sp++)
#pragma unroll
                for (int np = 0; np < 4; np++) {
                    const int r = wn * 64 + np * 16 + (lane & 15);
                    const uint32_t addr = sbase + SM_B + (st * 2 + sp) * 16384
                                        + r * 128 + ((cc ^ (r & 7)) * 16);
                    ldm_x4(bb[sp][np][0], bb[sp][np][1], bb[sp][np][2], bb[sp][np][3], addr);
                }
#pragma unroll
            for (int mt = 0; mt < 2; mt++)
#pragma unroll
                for (int nt = 0; nt < 8; nt++) {
                    const int np = nt >> 1, sel = nt & 1;
                    const uint32_t bh0 = bb[0][np][sel],     bh1 = bb[0][np][sel + 2];
                    const uint32_t bl0 = bb[1][np][sel],     bl1 = bb[1][np][sel + 2];
                    mma_bf16(acc[mt][nt], a[0][mt], bh0, bh1);   // hh
                    mma_bf16(acc[mt][nt], a[0][mt], bl0, bl1);   // hl
                    mma_bf16(acc[mt][nt], a[1][mt], bh0, bh1);   // lh
                }
        }
        __syncthreads();
    }

    // Epilogue: p = sum_cols relu(acc + b1) * w2, reduce across quads + wn.
#pragma unroll
    for (int mt = 0; mt < 2; mt++) {
        float p0 = 0.0f, p1 = 0.0f;
#pragma unroll
        for (int nt = 0; nt < 8; nt++) {
            const int cl = wn * 64 + nt * 8 + (lane & 3) * 2;
            const float w0 = w2s[cl], w1v = w2s[cl + 1];
            const float c0 = b1s[cl], c1 = b1s[cl + 1];
            p0 = fmaf(fmaxf(acc[mt][nt][0] + c0, 0.0f), w0, p0);
            p0 = fmaf(fmaxf(acc[mt][nt][1] + c1, 0.0f), w1v, p0);
            p1 = fmaf(fmaxf(acc[mt][nt][2] + c0, 0.0f), w0, p1);
            p1 = fmaf(fmaxf(acc[mt][nt][3] + c1, 0.0f), w1v, p1);
        }
        p0 += __shfl_xor_sync(0xffffffffu, p0, 1);
        p0 += __shfl_xor_sync(0xffffffffu, p0, 2);
        p1 += __shfl_xor_sync(0xffffffffu, p1, 1);
        p1 += __shfl_xor_sync(0xffffffffu, p1, 2);
        if ((lane & 3) == 0) {
            const int r0 = wm * 32 + mt * 16 + (lane >> 2);
            red[r0][wn] = p0;
            red[r0 + 8][wn] = p1;
        }
    }
    __syncthreads();
    if (tid < TM)
        g_yp[blockIdx.x][m0 + tid] = red[tid][0] + red[tid][1];
}

// ---------------------------------------------------------------------------
// Kernel B1: sum partials -> z, flag tokens within BAND of threshold.
// ---------------------------------------------------------------------------
__global__ __launch_bounds__(256, 8)
void zflag_kernel(const float* __restrict__ b2)
{
    const int t = blockIdx.x * 256 + threadIdx.x;
    float z = g_yp[0][t] + g_yp[1][t] + g_yp[2][t] + g_yp[3][t] + b2[0];
    g_z[t] = z;
    if (fabsf(z - ZTHR) < BAND) {
        int i = atomicAdd(&g_nflag, 1);
        if (i < MAXFLAG) g_flag[i] = t;
    }
}

// ---------------------------------------------------------------------------
// Kernel R: exact fp32 recompute of flagged tokens' logits.
// One block per flagged token (grid-stride). Thread owns h={tid, tid+256};
// W1 reads coalesced across threads, k-loop unrolled x8 for MLP.
// ---------------------------------------------------------------------------
__global__ __launch_bounds__(256, 1)
void refine_kernel(const float* __restrict__ X,
                   const float* __restrict__ W1,
                   const float* __restrict__ b1,
                   const float* __restrict__ W2,
                   const float* __restrict__ b2)
{
    __shared__ float xs[DD];
    __shared__ float rsum[256];
    const int tid = threadIdx.x;
    int n = g_nflag;
    if (n > MAXFLAG) n = MAXFLAG;

    for (int i = blockIdx.x; i < n; i += gridDim.x) {
        const int t = g_flag[i];
        for (int k = tid; k < DD; k += 256)
            xs[k] = X[(size_t)t * DD + k];
        __syncthreads();

        const int h0 = tid;
        const int h1 = tid + 256;
        float a0 = 0.0f, a1 = 0.0f;
#pragma unroll 8
        for (int k = 0; k < DD; k++) {
            const float xk = xs[k];
            a0 = fmaf(xk, W1[(size_t)k * DH + h0], a0);
            a1 = fmaf(xk, W1[(size_t)k * DH + h1], a1);
        }
        float p = fmaf(fmaxf(a0 + b1[h0], 0.0f), W2[h0], 0.0f);
        p = fmaf(fmaxf(a1 + b1[h1], 0.0f), W2[h1], p);
        rsum[tid] = p;
        __syncthreads();
        for (int o = 128; o > 0; o >>= 1) {
            if (tid < o) rsum[tid] += rsum[tid + o];
            __syncthreads();
        }
        if (tid == 0) g_z[t] = rsum[0] + b2[0];
        __syncthreads();
    }
}

// ---------------------------------------------------------------------------
// Kernel B2: per-batch squash, max/adjust, compaction.
// pad read as 4-byte (int32/float32): nonzero == padded.
// ---------------------------------------------------------------------------
__global__ __launch_bounds__(256, 1)
void gate_select_kernel(const unsigned int* __restrict__ pad,
                        float* __restrict__ vpad_out,
                        int write_vpad)
{
    const int b = blockIdx.x;
    const int tid = threadIdx.x;

    __shared__ float ysm[SQ];
    __shared__ int   ired[256];
    __shared__ float fred[256];
    __shared__ int   cnt[256];

    int lc = 0;
    for (int s = tid; s < SQ; s += 256)
        lc += (pad[b * SQ + s] == 0u) ? 1 : 0;
    ired[tid] = lc;
    __syncthreads();
    for (int o = 128; o > 0; o >>= 1) {
        if (tid < o) ired[tid] += ired[tid + o];
        __syncthreads();
    }
    const int length = ired[0];
    __syncthreads();

    float mx = 0.0f;
    for (int s = tid; s < SQ; s += 256) {
        float y = (s < length)
                ? (1.0f + tanhf(10.0f * g_z[b * SQ + s])) * 0.5f : 0.0f;
        ysm[s] = y;
        mx = fmaxf(mx, y);
    }
    fred[tid] = mx;
    __syncthreads();
    for (int o = 128; o > 0; o >>= 1) {
        if (tid < o) fred[tid] = fmaxf(fred[tid], fred[tid + o]);
        __syncthreads();
    }
    const float adjust = fmaxf(0.0f, EPSV + THRESHOLD - fred[0]);
    __syncthreads();

    for (int s = tid; s < SQ; s += 256) {
        float yf = ysm[s] + adjust;
        ysm[s] = yf;
        g_yfin[b * SQ + s] = yf;
    }
    __syncthreads();

    const int CH = SQ / 256;
    const int base = tid * CH;
    int c = 0;
#pragma unroll
    for (int i = 0; i < CH; i++) {
        int s = base + i;
        c += (ysm[s] > THRESHOLD && s < length) ? 1 : 0;
    }
    cnt[tid] = c;
    __syncthreads();
    for (int o = 1; o < 256; o <<= 1) {
        int v = (tid >= o) ? cnt[tid - o] : 0;
        __syncthreads();
        cnt[tid] += v;
        __syncthreads();
    }
    int off = cnt[tid] - c;
#pragma unroll
    for (int i = 0; i < CH; i++) {
        int s = base + i;
        if (ysm[s] > THRESHOLD && s < length) g_idx[b][off++] = s;
    }
    const int nl = cnt[255];
    if (tid == 0) g_newlen[b] = nl;

    if (write_vpad) {
        for (int s = tid; s < SQ; s += 256)
            vpad_out[b * SQ + s] = (s >= nl) ? 1.0f : 0.0f;
    }
}

// ---------------------------------------------------------------------------
// Kernel C: scatter compacted rows.
// ---------------------------------------------------------------------------
__global__ __launch_bounds__(256, 4)
void scatter_kernel(const float* __restrict__ X, float* __restrict__ V)
{
    const int b = blockIdx.y;
    const int r = blockIdx.x;
    const int tid = threadIdx.x;
    const int nl = g_newlen[b];

    float4* vrow = (float4*)(V + ((size_t)b * SQ + r) * DD);
    if (r < nl) {
        const int s = g_idx[b][r];
        const float g = g_yfin[b * SQ + s];
        const float4* xrow = (const float4*)(X + ((size_t)b * SQ + s) * DD);
        float4 xv = xrow[tid];
        vrow[tid] = make_float4(xv.x * g, xv.y * g, xv.z * g, xv.w * g);
    } else {
        vrow[tid] = make_float4(0.0f, 0.0f, 0.0f, 0.0f);
    }
}

// ---------------------------------------------------------------------------
extern "C" void kernel_launch(void* const* d_in, const int* in_sizes, int n_in,
                              void* d_out, int out_size)
{
    const float*        x   = (const float*)d_in[0];
    const unsigned int* pad = (const unsigned int*)d_in[1];
    const float*        W1  = (const float*)d_in[2];
    const float*        b1  = (const float*)d_in[3];
    const float*        W2  = (const float*)d_in[4];
    const float*        b2  = (const float*)d_in[5];
    float* out = (float*)d_out;

    const long v_elems = (long)MM * DD;
    int write_vpad = (out_size > v_elems) ? 1 : 0;
    float* vpad = out + v_elems;

    cudaFuncSetAttribute(gemm_hmma,
                         cudaFuncAttributeMaxDynamicSharedMemorySize, SM_TOT);

    w1_split_kernel<<<dim3(DD / 32, DH / 32), dim3(32, 8)>>>(W1);
    gemm_hmma<<<dim3(NG, MM / TM), 256, SM_TOT>>>(x, b1, W2);
    zflag_kernel<<<MM / 256, 256>>>(b2);
    refine_kernel<<<64, 256>>>(x, W1, b1, W2, b2);
    gate_select_kernel<<<BQ, 256>>>(pad, vpad, write_vpad);
    scatter_kernel<<<dim3(SQ, BQ), 256>>>(x, out);
}